// round 4
// baseline (speedup 1.0000x reference)
#include <cuda_runtime.h>
#include <cstdint>
#include <cstdio>

// Conv1d as implicit GEMM on tf32 mma.sync tensor cores.
// out[b, co, l] = sum_{ci,k} w[co,ci,k] * x[b,ci,l+k] + bias[co]
// B=32, Cin=64, L=16384, Cout=64, K=3, Lout=16382, fp32 I/O.

#define CIN   64
#define COUT  64
#define L_IN  16384
#define L_OUT 16382
#define BATCH 32
#define KTAPS 3
#define KDIM  (CIN * KTAPS)   // 192
#define LT    128             // output positions per CTA
#define LDX   136             // smem row stride (floats) for x tile; 136%32==8 -> conflict-free B loads
#define LDW   196             // smem row stride for weights;        196%32==4 -> conflict-free A loads
#define NTHREADS 256

// m16n8k8 tf32 mma, fp32 accumulate
#define MMA_TF32(d, a, b0_, b1_)                                              \
    asm volatile(                                                              \
        "mma.sync.aligned.m16n8k8.row.col.f32.tf32.tf32.f32 "                  \
        "{%0,%1,%2,%3}, {%4,%5,%6,%7}, {%8,%9}, {%0,%1,%2,%3};"                \
        : "+f"((d)[0]), "+f"((d)[1]), "+f"((d)[2]), "+f"((d)[3])               \
        : "r"((a)[0]), "r"((a)[1]), "r"((a)[2]), "r"((a)[3]),                  \
          "r"(b0_), "r"(b1_))

__device__ __forceinline__ uint32_t f32_to_tf32(float f) {
    uint32_t t;
    asm("cvt.rna.tf32.f32 %0, %1;" : "=r"(t) : "f"(f));
    return t;
}

__global__ __launch_bounds__(NTHREADS, 2)
void conv1d_tf32_kernel(const float* __restrict__ x,
                        const float* __restrict__ w,
                        const float* __restrict__ bias,
                        float* __restrict__ out)
{
    extern __shared__ uint32_t smem[];
    uint32_t* XS = smem;                    // [CIN][LDX]  x tile, tf32
    uint32_t* WS = smem + CIN * LDX;        // [COUT][LDW] weights reordered [m][tap*64+ci], tf32

    const int tid  = threadIdx.x;
    const int lane = tid & 31;
    const int wid  = tid >> 5;
    const int g    = lane >> 2;   // group id 0..7
    const int tig  = lane & 3;    // thread-in-group 0..3

    const int tile = blockIdx.x;            // 0..127
    const int b    = blockIdx.y;            // 0..31
    const int l0   = tile * LT;

    // ---- Fill x tile: CIN rows x (LT+2) cols, clamp OOB to 0, cvt to tf32 ----
    {
        const float* xb = x + (size_t)b * CIN * L_IN + l0;
        for (int row = wid; row < CIN; row += 8) {
            const float* xr = xb + (size_t)row * L_IN;
            uint32_t* xs = XS + row * LDX;
            #pragma unroll
            for (int col = lane; col < LT + 2; col += 32) {
                float v = (l0 + col < L_IN) ? xr[col] : 0.0f;
                xs[col] = f32_to_tf32(v);
            }
        }
    }
    // ---- Fill weights: WS[m][tap*64+ci] = w[m][ci][tap], cvt to tf32 ----
    for (int i = tid; i < COUT * KDIM; i += NTHREADS) {
        int m  = i / KDIM;
        int kk = i - m * KDIM;
        int tap = kk >> 6;
        int ci  = kk & 63;
        WS[m * LDW + kk] = f32_to_tf32(w[(m * CIN + ci) * KTAPS + tap]);
    }
    __syncthreads();

    // ---- Warp tiling: 2 (M) x 4 (N). Warp tile = 32 (M) x 32 (N). ----
    const int warp_m = wid & 1;      // 0..1
    const int warp_n = wid >> 1;     // 0..3
    const int mbase  = warp_m * 32;
    const int nbase  = warp_n * 32;

    float acc[2][4][4];
    #pragma unroll
    for (int mt = 0; mt < 2; mt++)
        #pragma unroll
        for (int nt = 0; nt < 4; nt++)
            #pragma unroll
            for (int r = 0; r < 4; r++)
                acc[mt][nt][r] = 0.0f;

    // ---- Main loop: 24 k-steps of 8 (3 taps x 8 ci-chunks) ----
    #pragma unroll
    for (int s = 0; s < KDIM / 8; s++) {
        const int tap = s >> 3;          // 0..2
        const int kb  = (s & 7) * 8;     // ci base within tap

        // A fragments (weights), m16k8 each, 2 m-tiles
        uint32_t a[2][4];
        #pragma unroll
        for (int mt = 0; mt < 2; mt++) {
            const uint32_t* wr = WS + (mbase + mt * 16 + g) * LDW + tap * 64 + kb + tig;
            a[mt][0] = wr[0];
            a[mt][1] = wr[8 * LDW];
            a[mt][2] = wr[4];
            a[mt][3] = wr[8 * LDW + 4];
        }

        // B fragments (x), k8n8 each, 4 n-tiles; fused with mma
        #pragma unroll
        for (int nt = 0; nt < 4; nt++) {
            const uint32_t* xsp = XS + (kb + tig) * LDX + nbase + nt * 8 + g + tap;
            uint32_t b0 = xsp[0];
            uint32_t b1 = xsp[4 * LDX];
            #pragma unroll
            for (int mt = 0; mt < 2; mt++)
                MMA_TF32(acc[mt][nt], a[mt], b0, b1);
        }
    }

    // ---- Epilogue: add bias, store (float2 per c-pair) ----
    #pragma unroll
    for (int mt = 0; mt < 2; mt++) {
        const int m0  = mbase + mt * 16 + g;
        const float bv0 = bias[m0];
        const float bv1 = bias[m0 + 8];
        float* o0 = out + ((size_t)b * COUT + m0) * L_OUT + l0;
        float* o1 = o0 + 8 * (size_t)L_OUT;
        #pragma unroll
        for (int nt = 0; nt < 4; nt++) {
            const int n = nbase + nt * 8 + 2 * tig;
            if (l0 + n < L_OUT) {
                float2 v0 = make_float2(acc[mt][nt][0] + bv0, acc[mt][nt][1] + bv0);
                float2 v1 = make_float2(acc[mt][nt][2] + bv1, acc[mt][nt][3] + bv1);
                *reinterpret_cast<float2*>(o0 + n) = v0;
                *reinterpret_cast<float2*>(o1 + n) = v1;
            }
        }
    }
}

extern "C" void kernel_launch(void* const* d_in, const int* in_sizes, int n_in,
                              void* d_out, int out_size)
{
    const float* x    = (const float*)d_in[0];
    const float* w    = (const float*)d_in[1];
    const float* bias = (const float*)d_in[2];
    float* out        = (float*)d_out;

    const int smem_bytes = (CIN * LDX + COUT * LDW) * 4;  // 84,992 B
    cudaFuncSetAttribute(conv1d_tf32_kernel,
                         cudaFuncAttributeMaxDynamicSharedMemorySize, smem_bytes);

    dim3 grid((L_OUT + LT - 1) / LT, BATCH);   // 128 x 32
    conv1d_tf32_kernel<<<grid, NTHREADS, smem_bytes>>>(x, w, bias, out);
}

// round 5
// speedup vs baseline: 2.0959x; 2.0959x over previous
#include <cuda_runtime.h>
#include <cstdint>

// Conv1d as implicit GEMM on tf32 mma.sync tensor cores.
// Persistent CTAs + preprocessed weights + cp.async double-buffered x tiles.
// out[b, co, l] = sum_{ci,k} w[co,ci,k] * x[b,ci,l+k] + bias[co]
// B=32, Cin=64, L=16384, Cout=64, K=3, Lout=16382, fp32 I/O.

#define CIN   64
#define COUT  64
#define L_IN  16384
#define L_OUT 16382
#define BATCH 32
#define KTAPS 3
#define KDIM  (CIN * KTAPS)        // 192
#define LT    96                   // output positions per tile
#define XCOLS (LT + 2)             // 98 input cols per tile
#define LDX   104                  // x smem row stride; 104%32==8 -> conflict-free B loads
#define LDW   196                  // w smem row stride; 196%32==4 -> conflict-free A loads
#define NTILES 171                 // ceil(16382/96)
#define UNITS  (BATCH * NTILES)    // 5472
#define GRID   304                 // 2 CTAs/SM on 152 SMs; 5472/304 == 18 exactly
#define ITERS  (UNITS / GRID)      // 18
#define NTHREADS 256

#define XBUF_U32 (CIN * LDX)               // 6656 u32 per x buffer
#define SMEM_U32 (COUT * LDW + 2 * XBUF_U32)  // 12544 + 13312 = 25856 u32 = 103424 B

// m16n8k8 tf32 mma, fp32 accumulate
#define MMA_TF32(d, a, b0_, b1_)                                              \
    asm volatile(                                                              \
        "mma.sync.aligned.m16n8k8.row.col.f32.tf32.tf32.f32 "                  \
        "{%0,%1,%2,%3}, {%4,%5,%6,%7}, {%8,%9}, {%0,%1,%2,%3};"                \
        : "+f"((d)[0]), "+f"((d)[1]), "+f"((d)[2]), "+f"((d)[3])               \
        : "r"((a)[0]), "r"((a)[1]), "r"((a)[2]), "r"((a)[3]),                  \
          "r"(b0_), "r"(b1_))

#define CP_ASYNC_16(dst_s, src_g, sz)                                          \
    asm volatile("cp.async.cg.shared.global [%0], [%1], 16, %2;"               \
                 :: "r"(dst_s), "l"(src_g), "r"(sz))
#define CP_ASYNC_4(dst_s, src_g, sz)                                           \
    asm volatile("cp.async.ca.shared.global [%0], [%1], 4, %2;"                \
                 :: "r"(dst_s), "l"(src_g), "r"(sz))
#define CP_COMMIT()  asm volatile("cp.async.commit_group;")
#define CP_WAIT(N)   asm volatile("cp.async.wait_group %0;" :: "n"(N))

// Reordered tf32 weights: [m][tap*64+ci]
__device__ __align__(16) uint32_t g_wtf32[COUT * KDIM];

__global__ void prep_weights(const float* __restrict__ w) {
    int i = blockIdx.x * blockDim.x + threadIdx.x;
    if (i < COUT * KDIM) {
        int m   = i / KDIM;
        int kk  = i - m * KDIM;
        int tap = kk >> 6;
        int ci  = kk & 63;
        uint32_t t;
        asm("cvt.rna.tf32.f32 %0, %1;" : "=r"(t) : "f"(w[(m * CIN + ci) * KTAPS + tap]));
        g_wtf32[i] = t;
    }
}

// Issue async load of one x tile (unit -> (b, t)) into buffer bufsel.
__device__ __forceinline__ void load_x_tile(const float* __restrict__ x,
                                            uint32_t xs_saddr_base, int bufsel,
                                            int unit, int tid)
{
    const int b  = unit / NTILES;
    const int t  = unit - b * NTILES;
    const int l0 = t * LT;

    const uint32_t xs = xs_saddr_base + (uint32_t)bufsel * (XBUF_U32 * 4);

    // Bulk: cols 0..95 as 16B chunks. thread -> (row = tid/4, q = tid&3), 6 chunks each.
    {
        const int row = tid >> 2;
        const int q   = tid & 3;
        const float* src = x + ((size_t)b * CIN + row) * L_IN + l0;
        const uint32_t dst = xs + (uint32_t)(row * LDX) * 4;
        #pragma unroll
        for (int j = 0; j < 6; j++) {
            const int col = 4 * q + 16 * j;          // 0..92 step 4
            const int sz  = (l0 + col < L_IN) ? 16 : 0;
            CP_ASYNC_16(dst + col * 4, src + col, sz);
        }
    }
    // Tail: cols 96, 97 (4B each), threads 0..127 cover 64 rows x 2 cols.
    if (tid < 128) {
        const int row = tid >> 1;
        const int col = XCOLS - 2 + (tid & 1);       // 96 or 97
        const float* src = x + ((size_t)b * CIN + row) * L_IN + l0 + col;
        const uint32_t dst = xs + (uint32_t)(row * LDX + col) * 4;
        const int sz = (l0 + col < L_IN) ? 4 : 0;
        CP_ASYNC_4(dst, src, sz);
    }
}

__global__ __launch_bounds__(NTHREADS, 2)
void conv1d_tf32_kernel(const float* __restrict__ x,
                        const float* __restrict__ bias,
                        float* __restrict__ out)
{
    extern __shared__ uint32_t smem[];
    uint32_t* WS = smem;                         // [COUT][LDW]
    uint32_t* XS = smem + COUT * LDW;            // [2][CIN][LDX]

    const int tid  = threadIdx.x;
    const int lane = tid & 31;
    const int wid  = tid >> 5;
    const int g    = lane >> 2;
    const int tig  = lane & 3;

    const uint32_t xs_saddr_base = (uint32_t)__cvta_generic_to_shared(XS);

    // ---- Prologue: kick off x tile 0 load, then fill weights from g_wtf32 ----
    int u = blockIdx.x;
    load_x_tile(x, xs_saddr_base, 0, u, tid);
    CP_COMMIT();

    // Weight smem fill: 3072 uint4, coalesced. WS row stride 196 u32 (784 B, 16B-aligned).
    {
        const uint4* wg = reinterpret_cast<const uint4*>(g_wtf32);
        #pragma unroll
        for (int j = 0; j < 12; j++) {
            int idx = tid + j * NTHREADS;            // 0..3071
            int m   = idx / 48;
            int c   = idx - m * 48;                  // uint4 index within row
            *reinterpret_cast<uint4*>(WS + m * LDW + c * 4) = wg[m * 48 + c];
        }
    }

    // ---- Warp tiling: 2 (M) x 4 (N). Warp tile = 32 (M) x 24 (N). ----
    const int warp_m = wid & 1;
    const int warp_n = wid >> 1;
    const int mbase  = warp_m * 32;
    const int nbase  = warp_n * 24;

    // Bias registers (constant across units)
    const float bv[2][2] = {
        { bias[mbase + g],      bias[mbase + g + 8]      },
        { bias[mbase + 16 + g], bias[mbase + 16 + g + 8] }
    };

    // ---- Persistent loop over 18 units, double-buffered ----
    for (int it = 0; it < ITERS; it++) {
        const int un = u + GRID;
        if (it + 1 < ITERS) {
            load_x_tile(x, xs_saddr_base, (it + 1) & 1, un, tid);
            CP_COMMIT();
            CP_WAIT(1);
        } else {
            CP_WAIT(0);
        }
        __syncthreads();

        const uint32_t* XC = XS + (it & 1) * XBUF_U32;
        const int b  = u / NTILES;
        const int t  = u - b * NTILES;
        const int l0 = t * LT;

        float acc[2][3][4];
        #pragma unroll
        for (int mt = 0; mt < 2; mt++)
            #pragma unroll
            for (int nt = 0; nt < 3; nt++)
                #pragma unroll
                for (int r = 0; r < 4; r++)
                    acc[mt][nt][r] = 0.0f;

        #pragma unroll
        for (int tap = 0; tap < KTAPS; tap++) {
            #pragma unroll
            for (int ck = 0; ck < 8; ck++) {
                const int kb = ck * 8;

                uint32_t a[2][4];
                #pragma unroll
                for (int mt = 0; mt < 2; mt++) {
                    const uint32_t* wr = WS + (mbase + mt * 16 + g) * LDW + tap * 64 + kb + tig;
                    a[mt][0] = wr[0];
                    a[mt][1] = wr[8 * LDW];
                    a[mt][2] = wr[4];
                    a[mt][3] = wr[8 * LDW + 4];
                }

                #pragma unroll
                for (int nt = 0; nt < 3; nt++) {
                    const uint32_t* xsp = XC + (kb + tig) * LDX + nbase + nt * 8 + g + tap;
                    uint32_t b0 = xsp[0];
                    uint32_t b1 = xsp[4 * LDX];
                    #pragma unroll
                    for (int mt = 0; mt < 2; mt++)
                        MMA_TF32(acc[mt][nt], a[mt], b0, b1);
                }
            }
        }

        // ---- Epilogue: bias + store float2 pairs ----
        #pragma unroll
        for (int mt = 0; mt < 2; mt++) {
            const int m0 = mbase + mt * 16 + g;
            float* o0 = out + ((size_t)b * COUT + m0) * L_OUT + l0;
            float* o1 = o0 + 8 * (size_t)L_OUT;
            #pragma unroll
            for (int nt = 0; nt < 3; nt++) {
                const int n = nbase + nt * 8 + 2 * tig;
                if (l0 + n < L_OUT) {
                    float2 v0 = make_float2(acc[mt][nt][0] + bv[mt][0],
                                            acc[mt][nt][1] + bv[mt][0]);
                    float2 v1 = make_float2(acc[mt][nt][2] + bv[mt][1],
                                            acc[mt][nt][3] + bv[mt][1]);
                    *reinterpret_cast<float2*>(o0 + n) = v0;
                    *reinterpret_cast<float2*>(o1 + n) = v1;
                }
            }
        }

        __syncthreads();   // protect buffer (it&1) before it is refilled at it+2
        u = un;
    }
}

extern "C" void kernel_launch(void* const* d_in, const int* in_sizes, int n_in,
                              void* d_out, int out_size)
{
    const float* x    = (const float*)d_in[0];
    const float* w    = (const float*)d_in[1];
    const float* bias = (const float*)d_in[2];
    float* out        = (float*)d_out;

    prep_weights<<<(COUT * KDIM + 255) / 256, 256>>>(w);

    const int smem_bytes = SMEM_U32 * 4;   // 103,424 B
    cudaFuncSetAttribute(conv1d_tf32_kernel,
                         cudaFuncAttributeMaxDynamicSharedMemorySize, smem_bytes);
    conv1d_tf32_kernel<<<GRID, NTHREADS, smem_bytes>>>(x, bias, out);
}